// round 4
// baseline (speedup 1.0000x reference)
#include <cuda_runtime.h>

// Collapsed SimpleAttention: out[b,k] = (mean_s x[b,s,:]) @ Wv[:,k] + bv[k]
// (softmax over the query axis => sum_q att[b,q,s] = 1 => Q/K/att cancel
//  exactly under the mean-pool).
//
// k1 : column-sum of x. grid (74,8)=592 blocks = exactly 4/SM (balanced wave),
//      8 independent float4 loads in flight per thread, no reg cap.
// k2a: reduce 74 partials -> xbar[b][d].
// k2b: GEMM, 64 blocks (8 ktile x 8 dslice). Wv read ONCE; each thread keeps
//      its 32 Wv values in registers and reuses across all 8 batches.
// k3 : sum 8 d-slice partials + bias -> d_out.

#define BB     8
#define SS     2048
#define DD     1024
#define DKK    512
#define NCHUNK 74                      // k1 blocks per batch; 8*74 = 592 = 4*148

__device__ float g_partial[BB * NCHUNK * DD];   // [b][chunk][d]  ~2.4 MB
__device__ float g_xbar[BB * DD];               // [b][d]
__device__ float g_part2[8 * BB * DKK];         // [dsl][b][k]    128 KB

// ---------------------------------------------------------------------------
// k1: block (j,b) sums rows [j*SS/74, (j+1)*SS/74) of x[b] (27 or 28 rows).
// ---------------------------------------------------------------------------
__global__ void __launch_bounds__(256) k1_colsum(const float* __restrict__ x) {
    const int j = blockIdx.x;
    const int b = blockIdx.y;
    const int d = threadIdx.x * 4;

    const int r0 = (j * SS) / NCHUNK;
    const int r1 = ((j + 1) * SS) / NCHUNK;
    const int n  = r1 - r0;

    const float4* xp = reinterpret_cast<const float4*>(
        x + ((size_t)(b * SS + r0)) * DD + d);
    const size_t rs = DD / 4;

    float4 a0 = make_float4(0.f, 0.f, 0.f, 0.f);
    float4 a1 = make_float4(0.f, 0.f, 0.f, 0.f);
    float4 a2 = make_float4(0.f, 0.f, 0.f, 0.f);
    float4 a3 = make_float4(0.f, 0.f, 0.f, 0.f);

    int s = 0;
    for (; s + 8 <= n; s += 8, xp += 8 * rs) {
        const float4 v0 = xp[0 * rs];
        const float4 v1 = xp[1 * rs];
        const float4 v2 = xp[2 * rs];
        const float4 v3 = xp[3 * rs];
        const float4 v4 = xp[4 * rs];
        const float4 v5 = xp[5 * rs];
        const float4 v6 = xp[6 * rs];
        const float4 v7 = xp[7 * rs];
        a0.x += v0.x; a0.y += v0.y; a0.z += v0.z; a0.w += v0.w;
        a1.x += v1.x; a1.y += v1.y; a1.z += v1.z; a1.w += v1.w;
        a2.x += v2.x; a2.y += v2.y; a2.z += v2.z; a2.w += v2.w;
        a3.x += v3.x; a3.y += v3.y; a3.z += v3.z; a3.w += v3.w;
        a0.x += v4.x; a0.y += v4.y; a0.z += v4.z; a0.w += v4.w;
        a1.x += v5.x; a1.y += v5.y; a1.z += v5.z; a1.w += v5.w;
        a2.x += v6.x; a2.y += v6.y; a2.z += v6.z; a2.w += v6.w;
        a3.x += v7.x; a3.y += v7.y; a3.z += v7.z; a3.w += v7.w;
    }
    for (; s < n; s++, xp += rs) {
        const float4 v = *xp;
        a0.x += v.x; a0.y += v.y; a0.z += v.z; a0.w += v.w;
    }
    a0.x += a1.x; a0.y += a1.y; a0.z += a1.z; a0.w += a1.w;
    a2.x += a3.x; a2.y += a3.y; a2.z += a3.z; a2.w += a3.w;
    a0.x += a2.x; a0.y += a2.y; a0.z += a2.z; a0.w += a2.w;

    *reinterpret_cast<float4*>(g_partial + ((size_t)(b * NCHUNK + j)) * DD + d) = a0;
}

// ---------------------------------------------------------------------------
// k2a: xbar[b][d] = (1/SS) * sum_j g_partial[b][j][d]. grid (4,8) x 256.
// ---------------------------------------------------------------------------
__global__ void __launch_bounds__(256) k2a_reduce() {
    const int b = blockIdx.y;
    const int d = blockIdx.x * 256 + threadIdx.x;
    const float* p = g_partial + (size_t)b * NCHUNK * DD + d;
    float s = 0.f;
#pragma unroll 2
    for (int j = 0; j < NCHUNK; j++)
        s += p[(size_t)j * DD];
    g_xbar[b * DD + d] = s * (1.0f / (float)SS);
}

// ---------------------------------------------------------------------------
// k2b: grid (8 ktile, 8 dslice), 256 thr. Block owns k range 64, d range 128.
// Thread: kk = t&63 (one k), dg = t>>6 (one of 4 d-groups of 32).
// Loads its 32 Wv values ONCE into registers, reuses for all 8 batches.
// Warp Wv reads: 32 consecutive k = 128B coalesced.
// ---------------------------------------------------------------------------
__global__ void __launch_bounds__(256) k2b_gemm(const float* __restrict__ Wv) {
    __shared__ float xbs[BB][128];
    __shared__ float red[4][BB][64];

    const int kt    = blockIdx.x;
    const int dsl   = blockIdx.y;
    const int t     = threadIdx.x;
    const int kbase = kt * 64;
    const int d0    = dsl * 128;
    const int kk    = t & 63;
    const int dg    = t >> 6;

    // load xbar slice for all batches: 8*128 = 1024 floats, float4 per thread
    {
        const int flat = t * 4;              // 0..1023
        const int b    = flat >> 7;
        const int dd   = flat & 127;
        *reinterpret_cast<float4*>(&xbs[b][dd]) =
            *reinterpret_cast<const float4*>(g_xbar + b * DD + d0 + dd);
    }
    __syncthreads();

    // 32 Wv values into registers (independent loads, high MLP)
    float w[32];
#pragma unroll
    for (int i = 0; i < 32; i++)
        w[i] = Wv[(size_t)(d0 + dg * 32 + i) * DKK + kbase + kk];

    // accumulate per batch, stage to smem
#pragma unroll
    for (int b = 0; b < BB; b++) {
        float a = 0.f;
#pragma unroll
        for (int i = 0; i < 32; i++)
            a += w[i] * xbs[b][dg * 32 + i];
        red[dg][b][kk] = a;
    }
    __syncthreads();

    // 256 threads reduce 512 outputs (8b x 64k): each thread 2 outputs
#pragma unroll
    for (int o = 0; o < 2; o++) {
        const int idx = t + o * 256;         // 0..511
        const int b   = idx >> 6;
        const int k   = idx & 63;
        float s = red[0][b][k] + red[1][b][k] + red[2][b][k] + red[3][b][k];
        g_part2[((size_t)dsl * BB + b) * DKK + kbase + k] = s;
    }
}

// ---------------------------------------------------------------------------
// k3: out[b][k] = bv[k] + sum_dsl g_part2[dsl][b][k]. grid 16 x 256.
// ---------------------------------------------------------------------------
__global__ void __launch_bounds__(256) k3_final(const float* __restrict__ bv,
                                                float* __restrict__ out) {
    const int idx = blockIdx.x * 256 + threadIdx.x;   // 0..4095
    const int b = idx / DKK;
    const int k = idx % DKK;
    float s = bv[k];
#pragma unroll
    for (int dsl = 0; dsl < 8; dsl++)
        s += g_part2[((size_t)dsl * BB + b) * DKK + k];
    out[idx] = s;
}

// ---------------------------------------------------------------------------
// Inputs (metadata order): x, Wq, bq, Wk, bk, Wv, bv
// ---------------------------------------------------------------------------
extern "C" void kernel_launch(void* const* d_in, const int* in_sizes, int n_in,
                              void* d_out, int out_size) {
    const float* x  = (const float*)d_in[0];
    const float* Wv = (const float*)d_in[5];
    const float* bv = (const float*)d_in[6];
    float* out = (float*)d_out;

    k1_colsum<<<dim3(NCHUNK, BB), 256>>>(x);
    k2a_reduce<<<dim3(4, BB), 256>>>();
    k2b_gemm<<<dim3(8, 8), 256>>>(Wv);
    k3_final<<<16, 256>>>(bv, out);
}

// round 5
// speedup vs baseline: 1.2911x; 1.2911x over previous
#include <cuda_runtime.h>

// Collapsed SimpleAttention: out[b,k] = (mean_s x[b,s,:]) @ Wv[:,k] + bv[k]
// (softmax over the query axis => sum_q att[b,q,s] = 1 => Q/K/att cancel
//  exactly under the mean-pool).
//
// SINGLE fused kernel (measured: each extra graph kernel node costs ~3-5us).
// Grid (74,8)=592 blocks. Software grid barriers via atomic counters.
// Deadlock-free: barrier waiters are a subset of already-running blocks and
// all other blocks arrive-and-exit unconditionally. Counters reset by the
// last finishing block => graph-replayable, deterministic.

#define BB     8
#define SS     2048
#define DD     1024
#define DKK    512
#define NCHUNK 74                       // blocks per batch
#define TOTB   (NCHUNK * BB)            // 592

__device__ float g_partial[BB * NCHUNK * DD];   // [b][chunk][d]
__device__ float g_xbar[BB * DD];               // [b][d]
__device__ float g_part2[8 * BB * DKK];         // [dsl][b][k]
__device__ unsigned g_c1 = 0, g_c2 = 0, g_c3 = 0, g_done = 0;

__device__ __forceinline__ void spin_until(unsigned* ctr, unsigned target) {
    while (atomicAdd(ctr, 0u) != target) __nanosleep(64);
}

__global__ void __launch_bounds__(256, 4)
fused_kernel(const float* __restrict__ x,
             const float* __restrict__ Wv,
             const float* __restrict__ bv,
             float* __restrict__ out) {
    __shared__ float4 sB[8][32];        // stage-2 reduce staging
    __shared__ float  xbs[BB][128];     // stage-3 xbar slice
    __shared__ float  red[4][BB][64];   // stage-3 dg reduce

    const int j = blockIdx.x;           // 0..73
    const int b = blockIdx.y;           // 0..7
    const int t = threadIdx.x;

    // ======================= Stage 1: column sum of x ======================
    {
        const int d  = t * 4;
        const int r0 = (j * SS) / NCHUNK;
        const int r1 = ((j + 1) * SS) / NCHUNK;
        const int n  = r1 - r0;

        const float4* xp = reinterpret_cast<const float4*>(
            x + ((size_t)(b * SS + r0)) * DD + d);
        const size_t rs = DD / 4;

        float4 a0 = make_float4(0.f, 0.f, 0.f, 0.f);
        float4 a1 = make_float4(0.f, 0.f, 0.f, 0.f);
        float4 a2 = make_float4(0.f, 0.f, 0.f, 0.f);
        float4 a3 = make_float4(0.f, 0.f, 0.f, 0.f);

        int s = 0;
        for (; s + 8 <= n; s += 8, xp += 8 * rs) {
            const float4 v0 = xp[0 * rs];
            const float4 v1 = xp[1 * rs];
            const float4 v2 = xp[2 * rs];
            const float4 v3 = xp[3 * rs];
            const float4 v4 = xp[4 * rs];
            const float4 v5 = xp[5 * rs];
            const float4 v6 = xp[6 * rs];
            const float4 v7 = xp[7 * rs];
            a0.x += v0.x; a0.y += v0.y; a0.z += v0.z; a0.w += v0.w;
            a1.x += v1.x; a1.y += v1.y; a1.z += v1.z; a1.w += v1.w;
            a2.x += v2.x; a2.y += v2.y; a2.z += v2.z; a2.w += v2.w;
            a3.x += v3.x; a3.y += v3.y; a3.z += v3.z; a3.w += v3.w;
            a0.x += v4.x; a0.y += v4.y; a0.z += v4.z; a0.w += v4.w;
            a1.x += v5.x; a1.y += v5.y; a1.z += v5.z; a1.w += v5.w;
            a2.x += v6.x; a2.y += v6.y; a2.z += v6.z; a2.w += v6.w;
            a3.x += v7.x; a3.y += v7.y; a3.z += v7.z; a3.w += v7.w;
        }
        for (; s < n; s++, xp += rs) {
            const float4 v = *xp;
            a0.x += v.x; a0.y += v.y; a0.z += v.z; a0.w += v.w;
        }
        a0.x += a1.x; a0.y += a1.y; a0.z += a1.z; a0.w += a1.w;
        a2.x += a3.x; a2.y += a3.y; a2.z += a3.z; a2.w += a3.w;
        a0.x += a2.x; a0.y += a2.y; a0.z += a2.z; a0.w += a2.w;

        *reinterpret_cast<float4*>(
            g_partial + ((size_t)(b * NCHUNK + j)) * DD + d) = a0;
    }
    __syncthreads();
    __threadfence();
    if (t == 0) atomicAdd(&g_c1, 1u);

    if (j >= 8) return;                 // 528 blocks done; 64 continue

    // ================= Barrier 1: wait for all 592 partials ================
    if (t == 0) spin_until(&g_c1, TOTB);
    __syncthreads();
    __threadfence();

    // ====== Stage 2: xbar[b][j*128 .. j*128+128) = reduce over chunks ======
    {
        const int g   = t & 31;         // float4 group within 128-d slice
        const int sub = t >> 5;         // chunk subset 0..7
        const float4* p = reinterpret_cast<const float4*>(
            g_partial + (size_t)(b * NCHUNK) * DD + j * 128) + g;
        float4 a = make_float4(0.f, 0.f, 0.f, 0.f);
        for (int c = sub; c < NCHUNK; c += 8) {
            const float4 v = p[(size_t)c * (DD / 4)];
            a.x += v.x; a.y += v.y; a.z += v.z; a.w += v.w;
        }
        sB[sub][g] = a;
    }
    __syncthreads();
    if (t < 32) {
        float4 a = sB[0][t];
#pragma unroll
        for (int i = 1; i < 8; i++) {
            a.x += sB[i][t].x; a.y += sB[i][t].y;
            a.z += sB[i][t].z; a.w += sB[i][t].w;
        }
        const float inv = 1.0f / (float)SS;
        a.x *= inv; a.y *= inv; a.z *= inv; a.w *= inv;
        *reinterpret_cast<float4*>(g_xbar + b * DD + j * 128 + t * 4) = a;
    }
    __syncthreads();
    __threadfence();
    if (t == 0) atomicAdd(&g_c2, 1u);

    // ===================== Barrier 2: wait for full xbar ===================
    if (t == 0) spin_until(&g_c2, 64u);
    __syncthreads();
    __threadfence();

    // == Stage 3: GEMM slice. block=(ktile=j, dsl=b). Wv cached in regs, ===
    // == reused across all 8 batches. =====================================
    {
        const int ktile = j;
        const int dsl   = b;
        const int kbase = ktile * 64;
        const int d0    = dsl * 128;
        const int kk    = t & 63;
        const int dg    = t >> 6;

        {   // xbar slice for all batches: 1024 floats, float4 per thread
            const int flat = t * 4;
            const int bb   = flat >> 7;
            const int dd   = flat & 127;
            *reinterpret_cast<float4*>(&xbs[bb][dd]) =
                *reinterpret_cast<const float4*>(g_xbar + bb * DD + d0 + dd);
        }
        __syncthreads();

        float w[32];
#pragma unroll
        for (int i = 0; i < 32; i++)
            w[i] = Wv[(size_t)(d0 + dg * 32 + i) * DKK + kbase + kk];

#pragma unroll
        for (int bb = 0; bb < BB; bb++) {
            float a = 0.f;
#pragma unroll
            for (int i = 0; i < 32; i++)
                a += w[i] * xbs[bb][dg * 32 + i];
            red[dg][bb][kk] = a;
        }
        __syncthreads();

#pragma unroll
        for (int o = 0; o < 2; o++) {
            const int idx = t + o * 256;     // 0..511
            const int bb  = idx >> 6;
            const int k   = idx & 63;
            g_part2[((size_t)dsl * BB + bb) * DKK + kbase + k] =
                red[0][bb][k] + red[1][bb][k] + red[2][bb][k] + red[3][bb][k];
        }
    }
    __threadfence();
    __syncthreads();
    if (t == 0) atomicAdd(&g_c3, 1u);

    if (j != 0) return;                 // 8 blocks (one per b) continue

    // ==================== Barrier 3: wait for all GEMM =====================
    if (t == 0) spin_until(&g_c3, 64u);
    __syncthreads();
    __threadfence();

    // ============ Stage 4: out[b][k] = bv[k] + sum_dsl part2 ==============
#pragma unroll
    for (int o = 0; o < 2; o++) {
        const int k = t + o * 256;          // 0..511
        float s = bv[k];
#pragma unroll
        for (int dsl = 0; dsl < 8; dsl++)
            s += g_part2[((size_t)dsl * BB + b) * DKK + k];
        out[(size_t)b * DKK + k] = s;
    }
    __syncthreads();

    // ================= Counter reset (last block of stage 4) ===============
    if (t == 0) {
        const unsigned old = atomicAdd(&g_done, 1u);
        if (old == BB - 1) {                // all stage-4 blocks finished
            g_c1 = 0; g_c2 = 0; g_c3 = 0; g_done = 0;
            __threadfence();
        }
    }
}

// ---------------------------------------------------------------------------
// Inputs (metadata order): x, Wq, bq, Wk, bk, Wv, bv
// ---------------------------------------------------------------------------
extern "C" void kernel_launch(void* const* d_in, const int* in_sizes, int n_in,
                              void* d_out, int out_size) {
    const float* x  = (const float*)d_in[0];
    const float* Wv = (const float*)d_in[5];
    const float* bv = (const float*)d_in[6];
    float* out = (float*)d_out;

    fused_kernel<<<dim3(NCHUNK, BB), 256>>>(x, Wv, bv, out);
}

// round 6
// speedup vs baseline: 1.2989x; 1.0061x over previous
#include <cuda_runtime.h>

// Collapsed SimpleAttention: out[b,k] = (mean_s x[b,s,:]) @ Wv[:,k] + bv[k]
// (softmax over the query axis => sum_q att[b,q,s] = 1 => Q/K/att cancel
//  exactly under the mean-pool).
//
// SINGLE fused kernel. Grid (74,8)=592 blocks = 4/SM balanced.
// Grid barriers: arrive = atomicAdd(+1); wait = VOLATILE LOAD polling
// (read-only polls don't contend with arrivals in the LTS atomic ALU,
//  unlike the previous atomicAdd(ctr,0) RMW polling).
// Deadlock-free: waiters are a subset of already-running blocks; all other
// blocks arrive-and-exit unconditionally. Last finisher resets counters.

#define BB     8
#define SS     2048
#define DD     1024
#define DKK    512
#define NCHUNK 74                       // blocks per batch
#define TOTB   (NCHUNK * BB)            // 592

__device__ float g_partial[BB * NCHUNK * DD];   // [b][chunk][d]
__device__ float g_xbar[BB * DD];               // [b][d]
__device__ float g_part2[8 * BB * DKK];         // [dsl][b][k]
__device__ unsigned g_c1 = 0, g_c2 = 0, g_c3 = 0, g_done = 0;

// Read-only spin: volatile load (normal L2 read path, no atomic-ALU slot).
__device__ __forceinline__ void spin_until(unsigned* ctr, unsigned target) {
    const volatile unsigned* p = (const volatile unsigned*)ctr;
    while (*p != target) __nanosleep(32);
}

__global__ void __launch_bounds__(256, 4)
fused_kernel(const float* __restrict__ x,
             const float* __restrict__ Wv,
             const float* __restrict__ bv,
             float* __restrict__ out) {
    __shared__ float4 sB[8][32];        // stage-2 reduce staging
    __shared__ float  xbs[BB][128];     // stage-3 xbar slice
    __shared__ float  red[4][BB][64];   // stage-3 dg reduce

    const int j = blockIdx.x;           // 0..73
    const int b = blockIdx.y;           // 0..7
    const int t = threadIdx.x;

    // ======================= Stage 1: column sum of x ======================
    {
        const int d  = t * 4;
        const int r0 = (j * SS) / NCHUNK;
        const int r1 = ((j + 1) * SS) / NCHUNK;
        const int n  = r1 - r0;

        const float4* xp = reinterpret_cast<const float4*>(
            x + ((size_t)(b * SS + r0)) * DD + d);
        const size_t rs = DD / 4;

        float4 a0 = make_float4(0.f, 0.f, 0.f, 0.f);
        float4 a1 = make_float4(0.f, 0.f, 0.f, 0.f);
        float4 a2 = make_float4(0.f, 0.f, 0.f, 0.f);
        float4 a3 = make_float4(0.f, 0.f, 0.f, 0.f);

        int s = 0;
        for (; s + 8 <= n; s += 8, xp += 8 * rs) {
            const float4 v0 = xp[0 * rs];
            const float4 v1 = xp[1 * rs];
            const float4 v2 = xp[2 * rs];
            const float4 v3 = xp[3 * rs];
            const float4 v4 = xp[4 * rs];
            const float4 v5 = xp[5 * rs];
            const float4 v6 = xp[6 * rs];
            const float4 v7 = xp[7 * rs];
            a0.x += v0.x; a0.y += v0.y; a0.z += v0.z; a0.w += v0.w;
            a1.x += v1.x; a1.y += v1.y; a1.z += v1.z; a1.w += v1.w;
            a2.x += v2.x; a2.y += v2.y; a2.z += v2.z; a2.w += v2.w;
            a3.x += v3.x; a3.y += v3.y; a3.z += v3.z; a3.w += v3.w;
            a0.x += v4.x; a0.y += v4.y; a0.z += v4.z; a0.w += v4.w;
            a1.x += v5.x; a1.y += v5.y; a1.z += v5.z; a1.w += v5.w;
            a2.x += v6.x; a2.y += v6.y; a2.z += v6.z; a2.w += v6.w;
            a3.x += v7.x; a3.y += v7.y; a3.z += v7.z; a3.w += v7.w;
        }
        for (; s < n; s++, xp += rs) {
            const float4 v = *xp;
            a0.x += v.x; a0.y += v.y; a0.z += v.z; a0.w += v.w;
        }
        a0.x += a1.x; a0.y += a1.y; a0.z += a1.z; a0.w += a1.w;
        a2.x += a3.x; a2.y += a3.y; a2.z += a3.z; a2.w += a3.w;
        a0.x += a2.x; a0.y += a2.y; a0.z += a2.z; a0.w += a2.w;

        *reinterpret_cast<float4*>(
            g_partial + ((size_t)(b * NCHUNK + j)) * DD + d) = a0;
    }
    __syncthreads();
    __threadfence();                    // release partials
    if (t == 0) atomicAdd(&g_c1, 1u);

    if (j >= 8) return;                 // 528 blocks done; 64 continue

    // ================= Barrier 1: wait for all 592 partials ================
    if (t == 0) spin_until(&g_c1, TOTB);
    __syncthreads();
    __threadfence();                    // acquire

    // ====== Stage 2: xbar[b][j*128 .. j*128+128) = reduce over chunks ======
    {
        const int g   = t & 31;         // float4 group within 128-d slice
        const int sub = t >> 5;         // chunk subset 0..7
        const float4* p = reinterpret_cast<const float4*>(
            g_partial + (size_t)(b * NCHUNK) * DD + j * 128) + g;
        float4 a = make_float4(0.f, 0.f, 0.f, 0.f);
        for (int c = sub; c < NCHUNK; c += 8) {
            const float4 v = p[(size_t)c * (DD / 4)];
            a.x += v.x; a.y += v.y; a.z += v.z; a.w += v.w;
        }
        sB[sub][g] = a;
    }
    __syncthreads();
    if (t < 32) {
        float4 a = sB[0][t];
#pragma unroll
        for (int i = 1; i < 8; i++) {
            a.x += sB[i][t].x; a.y += sB[i][t].y;
            a.z += sB[i][t].z; a.w += sB[i][t].w;
        }
        const float inv = 1.0f / (float)SS;
        a.x *= inv; a.y *= inv; a.z *= inv; a.w *= inv;
        *reinterpret_cast<float4*>(g_xbar + b * DD + j * 128 + t * 4) = a;
    }
    __syncthreads();
    __threadfence();                    // release xbar
    if (t == 0) atomicAdd(&g_c2, 1u);

    // ===================== Barrier 2: wait for full xbar ===================
    if (t == 0) spin_until(&g_c2, 64u);
    __syncthreads();
    __threadfence();                    // acquire

    // === Stage 3: GEMM slice. block=(ktile=j, dsl=b). Wv cached in regs, ===
    // === reused across all 8 batches. ======================================
    {
        const int ktile = j;
        const int dsl   = b;
        const int kbase = ktile * 64;
        const int d0    = dsl * 128;
        const int kk    = t & 63;
        const int dg    = t >> 6;

        {   // xbar slice for all batches: 1024 floats, float4 per thread
            const int flat = t * 4;
            const int bb   = flat >> 7;
            const int dd   = flat & 127;
            *reinterpret_cast<float4*>(&xbs[bb][dd]) =
                *reinterpret_cast<const float4*>(g_xbar + bb * DD + d0 + dd);
        }
        __syncthreads();

        float w[32];
#pragma unroll
        for (int i = 0; i < 32; i++)
            w[i] = Wv[(size_t)(d0 + dg * 32 + i) * DKK + kbase + kk];

#pragma unroll
        for (int bb = 0; bb < BB; bb++) {
            float a = 0.f;
#pragma unroll
            for (int i = 0; i < 32; i++)
                a += w[i] * xbs[bb][dg * 32 + i];
            red[dg][bb][kk] = a;
        }
        __syncthreads();

#pragma unroll
        for (int o = 0; o < 2; o++) {
            const int idx = t + o * 256;     // 0..511
            const int bb  = idx >> 6;
            const int k   = idx & 63;
            g_part2[((size_t)dsl * BB + bb) * DKK + kbase + k] =
                red[0][bb][k] + red[1][bb][k] + red[2][bb][k] + red[3][bb][k];
        }
    }
    __threadfence();                    // release part2
    __syncthreads();
    if (t == 0) atomicAdd(&g_c3, 1u);

    if (j != 0) return;                 // 8 blocks (one per b) continue

    // ==================== Barrier 3: wait for all GEMM =====================
    if (t == 0) spin_until(&g_c3, 64u);
    __syncthreads();
    __threadfence();                    // acquire

    // ============ Stage 4: out[b][k] = bv[k] + sum_dsl part2 ===============
#pragma unroll
    for (int o = 0; o < 2; o++) {
        const int k = t + o * 256;          // 0..511
        float s = bv[k];
#pragma unroll
        for (int dsl = 0; dsl < 8; dsl++)
            s += g_part2[((size_t)dsl * BB + b) * DKK + k];
        out[(size_t)b * DKK + k] = s;
    }
    __syncthreads();

    // ================= Counter reset (last block of stage 4) ===============
    if (t == 0) {
        const unsigned old = atomicAdd(&g_done, 1u);
        if (old == BB - 1) {                // all stage-4 blocks finished
            g_c1 = 0; g_c2 = 0; g_c3 = 0; g_done = 0;
            __threadfence();
        }
    }
}

// ---------------------------------------------------------------------------
// Inputs (metadata order): x, Wq, bq, Wk, bk, Wv, bv
// ---------------------------------------------------------------------------
extern "C" void kernel_launch(void* const* d_in, const int* in_sizes, int n_in,
                              void* d_out, int out_size) {
    const float* x  = (const float*)d_in[0];
    const float* Wv = (const float*)d_in[5];
    const float* bv = (const float*)d_in[6];
    float* out = (float*)d_out;

    fused_kernel<<<dim3(NCHUNK, BB), 256>>>(x, Wv, bv, out);
}